// round 3
// baseline (speedup 1.0000x reference)
#include <cuda_runtime.h>
#include <math_constants.h>

// Problem constants
#define B_SZ   8192
#define IN_DIM 132
#define IN_PAD 144          // 132 padded to multiple of 16
#define N1     2112
#define N2     4224
#define N3     8448
#define N4     4224
#define NQ     64           // ACTION_SIZE * REWARD_SIZE
#define A_SZ   16
#define R_SZ   4

// -------- device scratch (static, allocation-guard compliant) ------------
__device__ float g_x0 [(size_t)B_SZ * IN_PAD];     //  4.7 MB  padded concat(state,pref)
__device__ float g_w1p[(size_t)N1   * IN_PAD];     //  1.2 MB  padded w1
__device__ float g_h1 [(size_t)B_SZ * N1];         //  69 MB
__device__ float g_h2 [(size_t)B_SZ * N2];         // 138 MB   (reused for h4)
__device__ float g_h3 [(size_t)B_SZ * N3];         // 277 MB

// -------- input / weight padding kernels ---------------------------------
__global__ void build_x0_kernel(const float* __restrict__ state,
                                const float* __restrict__ pref)
{
    int i = blockIdx.x * blockDim.x + threadIdx.x;
    const int total = B_SZ * IN_PAD;
    if (i >= total) return;
    int r = i / IN_PAD, c = i % IN_PAD;
    float v = 0.0f;
    if (c < 128)      v = state[r * 128 + c];
    else if (c < 132) v = pref [r * 4 + (c - 128)];
    g_x0[i] = v;
}

__global__ void build_w1_kernel(const float* __restrict__ w1)
{
    int i = blockIdx.x * blockDim.x + threadIdx.x;
    const int total = N1 * IN_PAD;
    if (i >= total) return;
    int r = i / IN_PAD, c = i % IN_PAD;
    g_w1p[i] = (c < IN_DIM) ? w1[r * IN_DIM + c] : 0.0f;
}

// -------- tiled SGEMM:  C[M,N] = A[M,K] @ W[N,K]^T + bias  (opt. ReLU) ----
// Requirements: M % 128 == 0, K % 16 == 0 (N handled with guards).
template <bool RELU>
__global__ void __launch_bounds__(256, 2)
gemm_nt_bias(const float* __restrict__ A,
             const float* __restrict__ W,
             const float* __restrict__ bias,
             float* __restrict__ C,
             int M, int N, int K)
{
    __shared__ float As[16][136];   // [k][m], padded to dodge store conflicts
    __shared__ float Ws[16][136];   // [k][n]

    const int tid = threadIdx.x;
    const int tx  = tid & 15;       // col group (8 cols each)
    const int ty  = tid >> 4;       // row group (8 rows each)
    const int bm  = blockIdx.y * 128;
    const int bn  = blockIdx.x * 128;

    const int ldRow = tid >> 2;     // 0..63
    const int ldC4  = tid & 3;      // 0..3  (float4 slot within K-chunk of 16)

    float acc[8][8];
    #pragma unroll
    for (int i = 0; i < 8; i++)
        #pragma unroll
        for (int j = 0; j < 8; j++) acc[i][j] = 0.0f;

    // ---- prefetch first K-tile into registers -----------------------------
    float4 avp[2], wvp[2];
    #pragma unroll
    for (int s = 0; s < 2; s++) {
        const int row = ldRow + s * 64;
        avp[s] = *reinterpret_cast<const float4*>(
            &A[(size_t)(bm + row) * K + ldC4 * 4]);
        const int wrow = bn + row;
        wvp[s] = (wrow < N)
            ? *reinterpret_cast<const float4*>(&W[(size_t)wrow * K + ldC4 * 4])
            : make_float4(0.f, 0.f, 0.f, 0.f);
    }

    for (int kk = 0; kk < K; kk += 16) {
        // store prefetched tile to shared
        #pragma unroll
        for (int s = 0; s < 2; s++) {
            const int row = ldRow + s * 64;
            As[ldC4 * 4 + 0][row] = avp[s].x;
            As[ldC4 * 4 + 1][row] = avp[s].y;
            As[ldC4 * 4 + 2][row] = avp[s].z;
            As[ldC4 * 4 + 3][row] = avp[s].w;
            Ws[ldC4 * 4 + 0][row] = wvp[s].x;
            Ws[ldC4 * 4 + 1][row] = wvp[s].y;
            Ws[ldC4 * 4 + 2][row] = wvp[s].z;
            Ws[ldC4 * 4 + 3][row] = wvp[s].w;
        }
        __syncthreads();

        // prefetch NEXT K-tile while FMAs run
        const int kn = kk + 16;
        if (kn < K) {
            #pragma unroll
            for (int s = 0; s < 2; s++) {
                const int row = ldRow + s * 64;
                avp[s] = *reinterpret_cast<const float4*>(
                    &A[(size_t)(bm + row) * K + kn + ldC4 * 4]);
                const int wrow = bn + row;
                wvp[s] = (wrow < N)
                    ? *reinterpret_cast<const float4*>(&W[(size_t)wrow * K + kn + ldC4 * 4])
                    : make_float4(0.f, 0.f, 0.f, 0.f);
            }
        }

        #pragma unroll
        for (int k = 0; k < 16; k++) {
            float a[8], w[8];
            #pragma unroll
            for (int i = 0; i < 8; i++) a[i] = As[k][ty * 8 + i];
            #pragma unroll
            for (int j = 0; j < 8; j++) w[j] = Ws[k][tx * 8 + j];
            #pragma unroll
            for (int i = 0; i < 8; i++)
                #pragma unroll
                for (int j = 0; j < 8; j++)
                    acc[i][j] = fmaf(a[i], w[j], acc[i][j]);
        }
        __syncthreads();
    }

    // epilogue: bias (+ReLU), vectorized float4 stores (8 consecutive cols/thread)
    const int colBase = bn + tx * 8;
    if (colBase + 7 < N) {
        float bv[8];
        #pragma unroll
        for (int j = 0; j < 8; j++) bv[j] = bias[colBase + j];
        #pragma unroll
        for (int i = 0; i < 8; i++) {
            float v[8];
            #pragma unroll
            for (int j = 0; j < 8; j++) {
                v[j] = acc[i][j] + bv[j];
                if (RELU) v[j] = fmaxf(v[j], 0.0f);
            }
            float* cp = &C[(size_t)(bm + ty * 8 + i) * N + colBase];
            *reinterpret_cast<float4*>(cp + 0) = make_float4(v[0], v[1], v[2], v[3]);
            *reinterpret_cast<float4*>(cp + 4) = make_float4(v[4], v[5], v[6], v[7]);
        }
    } else {
        #pragma unroll
        for (int j = 0; j < 8; j++) {
            const int col = colBase + j;
            if (col >= N) continue;
            const float bv = bias[col];
            #pragma unroll
            for (int i = 0; i < 8; i++) {
                float v = acc[i][j] + bv;
                if (RELU) v = fmaxf(v, 0.0f);
                C[(size_t)(bm + ty * 8 + i) * N + col] = v;
            }
        }
    }
}

// -------- envelope operator H: hq[i] = q[i, argmax_a <q[i,a,:],pref[i,:]>,:]
__global__ void envelope_kernel(const float* __restrict__ q,
                                const float* __restrict__ pref,
                                float* __restrict__ hq)
{
    int i = blockIdx.x * blockDim.x + threadIdx.x;
    if (i >= B_SZ) return;
    const float4 p = *reinterpret_cast<const float4*>(&pref[i * 4]);
    const float* qi = q + (size_t)i * NQ;
    float best = -CUDART_INF_F;
    int   ba   = 0;
    #pragma unroll
    for (int a = 0; a < A_SZ; a++) {
        const float4 qa = *reinterpret_cast<const float4*>(&qi[a * 4]);
        const float ip = qa.x * p.x + qa.y * p.y + qa.z * p.z + qa.w * p.w;
        if (ip > best) { best = ip; ba = a; }   // strict > = first-tie, matches argmax
    }
    *reinterpret_cast<float4*>(&hq[i * 4]) =
        *reinterpret_cast<const float4*>(&qi[ba * 4]);
}

// -------------------------- launch ---------------------------------------
extern "C" void kernel_launch(void* const* d_in, const int* in_sizes, int n_in,
                              void* d_out, int out_size)
{
    const float* state = (const float*)d_in[0];   // [8192,128]
    const float* pref  = (const float*)d_in[1];   // [8192,4]
    const float* w1    = (const float*)d_in[2];   // [2112,132]
    const float* b1    = (const float*)d_in[3];
    const float* w2    = (const float*)d_in[4];   // [4224,2112]
    const float* b2    = (const float*)d_in[5];
    const float* w3    = (const float*)d_in[6];   // [8448,4224]
    const float* b3    = (const float*)d_in[7];
    const float* w4    = (const float*)d_in[8];   // [4224,8448]
    const float* b4    = (const float*)d_in[9];
    const float* wq    = (const float*)d_in[10];  // [64,4224]
    const float* bq    = (const float*)d_in[11];

    float* out_hq = (float*)d_out;                       // [8192,4]
    float* out_q  = (float*)d_out + (size_t)B_SZ * R_SZ; // [8192,16,4]

    float *p_x0, *p_w1p, *p_h1, *p_h2, *p_h3;
    cudaGetSymbolAddress((void**)&p_x0,  g_x0);
    cudaGetSymbolAddress((void**)&p_w1p, g_w1p);
    cudaGetSymbolAddress((void**)&p_h1,  g_h1);
    cudaGetSymbolAddress((void**)&p_h2,  g_h2);
    cudaGetSymbolAddress((void**)&p_h3,  g_h3);

    // pad inputs
    build_x0_kernel<<<(B_SZ * IN_PAD + 255) / 256, 256>>>(state, pref);
    build_w1_kernel<<<(N1 * IN_PAD + 255) / 256, 256>>>(w1);

    const int MB = B_SZ / 128;  // 64 row tiles

    // layer 1: [8192,144] @ [2112,144]^T -> h1
    gemm_nt_bias<true ><<<dim3((N1 + 127) / 128, MB), 256>>>(p_x0, p_w1p, b1, p_h1, B_SZ, N1, IN_PAD);
    // layer 2: h1 @ w2^T -> h2
    gemm_nt_bias<true ><<<dim3((N2 + 127) / 128, MB), 256>>>(p_h1, w2, b2, p_h2, B_SZ, N2, N1);
    // layer 3: h2 @ w3^T -> h3
    gemm_nt_bias<true ><<<dim3((N3 + 127) / 128, MB), 256>>>(p_h2, w3, b3, p_h3, B_SZ, N3, N2);
    // layer 4: h3 @ w4^T -> h4 (reuse h2 buffer)
    gemm_nt_bias<true ><<<dim3((N4 + 127) / 128, MB), 256>>>(p_h3, w4, b4, p_h2, B_SZ, N4, N3);
    // q head: h4 @ wq^T -> q (no relu), straight into output slot
    gemm_nt_bias<false><<<dim3((NQ + 127) / 128, MB), 256>>>(p_h2, wq, bq, out_q, B_SZ, NQ, N4);

    // envelope
    envelope_kernel<<<(B_SZ + 255) / 256, 256>>>(out_q, pref, out_hq);
}

// round 6
// speedup vs baseline: 2.7854x; 2.7854x over previous
#include <cuda_runtime.h>
#include <cuda_bf16.h>
#include <math_constants.h>
#include <cstdint>

// ---------------- problem constants --------------------------------------
#define B_SZ   8192
#define K1P    192        // 132 padded to mult of 32
#define N1R    2112
#define N1P    2176       // 17*128
#define N2     4224
#define N3     8448
#define N4     4224
#define NQR    64
#define NQP    128
#define A_SZ   16

// ---------------- device scratch (bf16 hi/lo split arrays) ---------------
#define DECL(name, elems) __device__ __align__(16) __nv_bfloat16 name[(size_t)(elems)]
DECL(g_x0h, B_SZ * K1P);      DECL(g_x0l, B_SZ * K1P);
DECL(g_w1h, N1P * K1P);       DECL(g_w1l, N1P * K1P);
DECL(g_w2h, (size_t)N2 * N1P);DECL(g_w2l, (size_t)N2 * N1P);
DECL(g_w3h, (size_t)N3 * N2); DECL(g_w3l, (size_t)N3 * N2);
DECL(g_w4h, (size_t)N4 * N3); DECL(g_w4l, (size_t)N4 * N3);
DECL(g_wqh, (size_t)NQP * N4);DECL(g_wql, (size_t)NQP * N4);
DECL(g_h1h, (size_t)B_SZ * N1P); DECL(g_h1l, (size_t)B_SZ * N1P);
DECL(g_h2h, (size_t)B_SZ * N2);  DECL(g_h2l, (size_t)B_SZ * N2);   // reused for h4
DECL(g_h3h, (size_t)B_SZ * N3);  DECL(g_h3l, (size_t)B_SZ * N3);

// ---------------- PTX helpers (all base sm_80-era, no arch-conditional) --
__device__ __forceinline__ uint32_t smem_u32(const void* p) {
    uint32_t a;
    asm("{ .reg .u64 t; cvta.to.shared.u64 t, %1; cvt.u32.u64 %0, t; }" : "=r"(a) : "l"(p));
    return a;
}
__device__ __forceinline__ void cp16(uint32_t s, const void* g) {
    asm volatile("cp.async.cg.shared.global [%0], [%1], 16;" :: "r"(s), "l"(g));
}
__device__ __forceinline__ void cp_commit() {
    asm volatile("cp.async.commit_group;" ::: "memory");
}
__device__ __forceinline__ void cp_wait1() {
    asm volatile("cp.async.wait_group 1;" ::: "memory");
}
__device__ __forceinline__ void cp_wait0() {
    asm volatile("cp.async.wait_group 0;" ::: "memory");
}
__device__ __forceinline__ void ldsm_x4(uint32_t& r0, uint32_t& r1, uint32_t& r2, uint32_t& r3,
                                        uint32_t addr) {
    asm volatile("ldmatrix.sync.aligned.m8n8.x4.shared.b16 {%0,%1,%2,%3}, [%4];"
                 : "=r"(r0), "=r"(r1), "=r"(r2), "=r"(r3) : "r"(addr));
}
__device__ __forceinline__ void mma_bf16(float* c, const uint32_t* a, const uint32_t* b) {
    asm volatile("mma.sync.aligned.m16n8k16.row.col.f32.bf16.bf16.f32 "
                 "{%0,%1,%2,%3}, {%4,%5,%6,%7}, {%8,%9}, {%0,%1,%2,%3};"
                 : "+f"(c[0]), "+f"(c[1]), "+f"(c[2]), "+f"(c[3])
                 : "r"(a[0]), "r"(a[1]), "r"(a[2]), "r"(a[3]), "r"(b[0]), "r"(b[1]));
}

// ---------------- split / pad kernels ------------------------------------
__device__ __forceinline__ void split_store(float v, __nv_bfloat16* hi, __nv_bfloat16* lo, size_t i) {
    __nv_bfloat16 h = __float2bfloat16(v);
    hi[i] = h;
    lo[i] = __float2bfloat16(v - __bfloat162float(h));
}

__global__ void split_x0_kernel(const float* __restrict__ state, const float* __restrict__ pref) {
    int i = blockIdx.x * blockDim.x + threadIdx.x;
    if (i >= B_SZ * K1P) return;
    int r = i / K1P, c = i % K1P;
    float v = 0.0f;
    if (c < 128)      v = state[r * 128 + c];
    else if (c < 132) v = pref[r * 4 + (c - 128)];
    split_store(v, g_x0h, g_x0l, i);
}

__global__ void split_w_kernel(const float* __restrict__ src, int R, int C, int Cp,
                               __nv_bfloat16* __restrict__ hi, __nv_bfloat16* __restrict__ lo,
                               int total) {
    int i = blockIdx.x * blockDim.x + threadIdx.x;
    if (i >= total) return;
    int r = i / Cp, c = i % Cp;
    float v = (r < R && c < C) ? src[(size_t)r * C + c] : 0.0f;
    split_store(v, hi, lo, i);
}

// ---------------- HMMA GEMM: C = A @ W^T (bf16x3 split precision) --------
// A: [8192 x Kp] hi/lo, W: [Npad x Kp] hi/lo, K-major, Kp % 32 == 0.
// CTA tile 128x128, 8 warps (2 m x 4 n), warp tile 64x32.
// SMEM rows padded: 32 bf16 -> 40 (80B, 16B-aligned, LDSM conflict-free).
#define ROWB   80
#define TILEB  (128 * ROWB)       // 10240 per array
#define STAGEB (4 * TILEB)        // 40960 per stage (Ah,Al,Wh,Wl)

template <bool RELU, bool SPLIT_OUT>
__global__ void __launch_bounds__(256)
gemm_hmma(const __nv_bfloat16* __restrict__ Ah, const __nv_bfloat16* __restrict__ Al,
          const __nv_bfloat16* __restrict__ Wh, const __nv_bfloat16* __restrict__ Wl,
          const float* __restrict__ bias, int Kp, int Nreal,
          __nv_bfloat16* __restrict__ outH, __nv_bfloat16* __restrict__ outL, int outKp,
          float* __restrict__ outF)
{
    extern __shared__ char smem[];
    const uint32_t sb = smem_u32(smem);

    const int tid = threadIdx.x, wid = tid >> 5, lane = tid & 31;

    // ---- L2 supertile block remap: 8 n-cols sweep all m before advancing
    const int NBb = gridDim.x, MBb = gridDim.y;
    {
    }
    const int lidb = blockIdx.y * NBb + blockIdx.x;
    const int per  = 8 * MBb;
    const int gi   = lidb / per;
    const int rr   = lidb % per;
    const int remN = NBb - gi * 8;
    const int gN   = remN < 8 ? remN : 8;
    const int bn   = (gi * 8 + rr % gN) * 128;
    const int bm   = (rr / gN) * 128;

    // ---- accumulators: warp 64x32 = 4(m16) x 4(n8) mma tiles
    float acc[4][4][4];
    #pragma unroll
    for (int mi = 0; mi < 4; mi++)
        #pragma unroll
        for (int ni = 0; ni < 4; ni++)
            #pragma unroll
            for (int e = 0; e < 4; e++) acc[mi][ni][e] = 0.0f;

    const int warp_m = wid & 1, warp_n = wid >> 1;

    // ---- per-lane LDSM addressing precompute
    const int mat   = lane >> 3;       // which 8x8 matrix this lane feeds
    const int mrow8 = lane & 7;
    // A: rows += (mat&1)*8, kbyte += (mat>>1)*16
    const int a_rowoff = warp_m * 64 + (mat & 1) * 8 + mrow8;
    const int a_koff   = (mat >> 1) * 16;
    // B: rows += (mat>>1)*8, kbyte += (mat&1)*16
    const int b_rowoff = warp_n * 32 + (mat >> 1) * 8 + mrow8;
    const int b_koff   = (mat & 1) * 16;

    const int nch = Kp >> 5;

    // ---- stage loader (cp.async, 16B granules)
    auto load_stage = [&](int ch, int buf) {
        const int kk = ch << 5;
        const uint32_t base = sb + buf * STAGEB;
        #pragma unroll
        for (int s = 0; s < 2; s++) {
            const int g   = tid + s * 256;      // 0..511
            const int row = g >> 2;
            const int cb  = (g & 3) << 4;       // col byte offset 0/16/32/48
            const int ce  = cb >> 1;            // element offset
            const uint32_t so = base + row * ROWB + cb;
            const size_t ga = (size_t)(bm + row) * Kp + kk + ce;
            const size_t gb = (size_t)(bn + row) * Kp + kk + ce;
            cp16(so + 0 * TILEB, Ah + ga);
            cp16(so + 1 * TILEB, Al + ga);
            cp16(so + 2 * TILEB, Wh + gb);
            cp16(so + 3 * TILEB, Wl + gb);
        }
        cp_commit();
    };

    load_stage(0, 0);

    for (int ch = 0; ch < nch; ch++) {
        if (ch + 1 < nch) { load_stage(ch + 1, (ch + 1) & 1); cp_wait1(); }
        else              { cp_wait0(); }
        __syncthreads();

        const uint32_t base = sb + (ch & 1) * STAGEB;
        const uint32_t aHb = base, aLb = base + TILEB;
        const uint32_t wHb = base + 2 * TILEB, wLb = base + 3 * TILEB;

        #pragma unroll
        for (int ks = 0; ks < 2; ks++) {
            const int kb = ks * 32;   // 16 bf16 = 32B per kstep

            uint32_t a_h[4][4], a_l[4][4];
            #pragma unroll
            for (int mi = 0; mi < 4; mi++) {
                const uint32_t off = (uint32_t)(a_rowoff + mi * 16) * ROWB + kb + a_koff;
                ldsm_x4(a_h[mi][0], a_h[mi][1], a_h[mi][2], a_h[mi][3], aHb + off);
                ldsm_x4(a_l[mi][0], a_l[mi][1], a_l[mi][2], a_l[mi][3], aLb + off);
            }
            uint32_t b_h[4][2], b_l[4][2];
            #pragma unroll
            for (int nj = 0; nj < 2; nj++) {
                const uint32_t off = (uint32_t)(b_rowoff + nj * 16) * ROWB + kb + b_koff;
                ldsm_x4(b_h[nj*2][0], b_h[nj*2][1], b_h[nj*2+1][0], b_h[nj*2+1][1], wHb + off);
                ldsm_x4(b_l[nj*2][0], b_l[nj*2][1], b_l[nj*2+1][0], b_l[nj*2+1][1], wLb + off);
            }

            #pragma unroll
            for (int mi = 0; mi < 4; mi++)
                #pragma unroll
                for (int ni = 0; ni < 4; ni++) {
                    mma_bf16(acc[mi][ni], a_h[mi], b_h[ni]);
                    mma_bf16(acc[mi][ni], a_h[mi], b_l[ni]);
                    mma_bf16(acc[mi][ni], a_l[mi], b_h[ni]);
                }
        }
        __syncthreads();
    }

    // ---- epilogue: bias + ReLU, split to bf16 hi/lo (or fp32 out)
    const int qrow = lane >> 2, qcol = (lane & 3) * 2;
    #pragma unroll
    for (int mi = 0; mi < 4; mi++) {
        #pragma unroll
        for (int ni = 0; ni < 4; ni++) {
            const int r0 = bm + warp_m * 64 + mi * 16 + qrow;
            const int c0 = bn + warp_n * 32 + ni * 8 + qcol;
            #pragma unroll
            for (int e = 0; e < 4; e++) {
                const int row = r0 + (e >> 1) * 8;
                const int col = c0 + (e & 1);
                float v = acc[mi][ni][e] + ((col < Nreal) ? bias[col] : 0.0f);
                if (RELU) v = fmaxf(v, 0.0f);
                if (SPLIT_OUT) {
                    split_store(v, outH, outL, (size_t)row * outKp + col);
                } else {
                    if (col < Nreal)
                        outF[(size_t)row * Nreal + col] = v;
                }
            }
        }
    }
}

// ---------------- envelope operator H ------------------------------------
__global__ void envelope_kernel(const float* __restrict__ q,
                                const float* __restrict__ pref,
                                float* __restrict__ hq)
{
    int i = blockIdx.x * blockDim.x + threadIdx.x;
    if (i >= B_SZ) return;
    const float4 p = *reinterpret_cast<const float4*>(&pref[i * 4]);
    const float* qi = q + (size_t)i * NQR;
    float best = -CUDART_INF_F;
    int ba = 0;
    #pragma unroll
    for (int a = 0; a < A_SZ; a++) {
        const float4 qa = *reinterpret_cast<const float4*>(&qi[a * 4]);
        const float ip = qa.x * p.x + qa.y * p.y + qa.z * p.z + qa.w * p.w;
        if (ip > best) { best = ip; ba = a; }
    }
    *reinterpret_cast<float4*>(&hq[i * 4]) = *reinterpret_cast<const float4*>(&qi[ba * 4]);
}

// ---------------- launch --------------------------------------------------
extern "C" void kernel_launch(void* const* d_in, const int* in_sizes, int n_in,
                              void* d_out, int out_size)
{
    const float* state = (const float*)d_in[0];
    const float* pref  = (const float*)d_in[1];
    const float* w1 = (const float*)d_in[2];  const float* b1 = (const float*)d_in[3];
    const float* w2 = (const float*)d_in[4];  const float* b2 = (const float*)d_in[5];
    const float* w3 = (const float*)d_in[6];  const float* b3 = (const float*)d_in[7];
    const float* w4 = (const float*)d_in[8];  const float* b4 = (const float*)d_in[9];
    const float* wq = (const float*)d_in[10]; const float* bq = (const float*)d_in[11];

    float* out_hq = (float*)d_out;
    float* out_q  = (float*)d_out + (size_t)B_SZ * 4;

    #define SYM(p, s) __nv_bfloat16* p; cudaGetSymbolAddress((void**)&p, s)
    SYM(x0h, g_x0h); SYM(x0l, g_x0l);
    SYM(w1h, g_w1h); SYM(w1l, g_w1l);
    SYM(w2h, g_w2h); SYM(w2l, g_w2l);
    SYM(w3h, g_w3h); SYM(w3l, g_w3l);
    SYM(w4h, g_w4h); SYM(w4l, g_w4l);
    SYM(wqh, g_wqh); SYM(wql, g_wql);
    SYM(h1h, g_h1h); SYM(h1l, g_h1l);
    SYM(h2h, g_h2h); SYM(h2l, g_h2l);
    SYM(h3h, g_h3h); SYM(h3l, g_h3l);
    #undef SYM

    const int SMEM = 2 * STAGEB;   // 81920 B double-buffered
    cudaFuncSetAttribute(gemm_hmma<true,  true >, cudaFuncAttributeMaxDynamicSharedMemorySize, SMEM);
    cudaFuncSetAttribute(gemm_hmma<false, false>, cudaFuncAttributeMaxDynamicSharedMemorySize, SMEM);

    // ---- split/pad inputs & weights into bf16 hi/lo ----
    auto grd = [](long long n) { return (int)((n + 255) / 256); };
    split_x0_kernel<<<grd((long long)B_SZ * K1P), 256>>>(state, pref);
    split_w_kernel<<<grd((long long)N1P * K1P), 256>>>(w1, N1R, 132, K1P, w1h, w1l, N1P * K1P);
    split_w_kernel<<<grd((long long)N2 * N1P), 256>>>(w2, N2, N1R, N1P, w2h, w2l, N2 * N1P);
    split_w_kernel<<<grd((long long)N3 * N2),  256>>>(w3, N3, N2, N2, w3h, w3l, N3 * N2);
    split_w_kernel<<<grd((long long)N4 * N3),  256>>>(w4, N4, N3, N3, w4h, w4l, N4 * N3);
    split_w_kernel<<<grd((long long)NQP * N4), 256>>>(wq, NQR, N4, N4, wqh, wql, NQP * N4);

    const int MB = B_SZ / 128;  // 64

    // layer 1: x0[8192,192] @ w1^T -> h1 [8192, 2176]
    gemm_hmma<true, true><<<dim3(N1P / 128, MB), 256, SMEM>>>(
        x0h, x0l, w1h, w1l, b1, K1P, N1R, h1h, h1l, N1P, nullptr);
    // layer 2: h1 @ w2^T -> h2 [8192, 4224]
    gemm_hmma<true, true><<<dim3(N2 / 128, MB), 256, SMEM>>>(
        h1h, h1l, w2h, w2l, b2, N1P, N2, h2h, h2l, N2, nullptr);
    // layer 3: h2 @ w3^T -> h3 [8192, 8448]
    gemm_hmma<true, true><<<dim3(N3 / 128, MB), 256, SMEM>>>(
        h2h, h2l, w3h, w3l, b3, N2, N3, h3h, h3l, N3, nullptr);
    // layer 4: h3 @ w4^T -> h4 (reuse h2 arrays) [8192, 4224]
    gemm_hmma<true, true><<<dim3(N4 / 128, MB), 256, SMEM>>>(
        h3h, h3l, w4h, w4l, b4, N3, N4, h2h, h2l, N4, nullptr);
    // q head: h4 @ wq^T -> out_q fp32 [8192, 64]
    gemm_hmma<false, false><<<dim3(NQP / 128, MB), 256, SMEM>>>(
        h2h, h2l, wqh, wql, bq, N4, NQR, nullptr, nullptr, 0, out_q);

    envelope_kernel<<<(B_SZ + 255) / 256, 256>>>(out_q, pref, out_hq);
}

// round 7
// speedup vs baseline: 2.9642x; 1.0642x over previous
#include <cuda_runtime.h>
#include <cuda_bf16.h>
#include <math_constants.h>
#include <cstdint>

// ---------------- problem constants --------------------------------------
#define B_SZ   8192
#define K1P    192        // 132 padded to mult of 32
#define N1R    2112
#define N1P    2176       // 17*128
#define N2     4224
#define N3     8448
#define N4     4224
#define NQR    64
#define NQP    128
#define A_SZ   16

// ---------------- device scratch (bf16 hi/lo split arrays) ---------------
#define DECL(name, elems) __device__ __align__(16) __nv_bfloat16 name[(size_t)(elems)]
DECL(g_x0h, B_SZ * K1P);      DECL(g_x0l, B_SZ * K1P);
DECL(g_w1h, N1P * K1P);       DECL(g_w1l, N1P * K1P);
DECL(g_w2h, (size_t)N2 * N1P);DECL(g_w2l, (size_t)N2 * N1P);
DECL(g_w3h, (size_t)N3 * N2); DECL(g_w3l, (size_t)N3 * N2);
DECL(g_w4h, (size_t)N4 * N3); DECL(g_w4l, (size_t)N4 * N3);
DECL(g_wqh, (size_t)NQP * N4);DECL(g_wql, (size_t)NQP * N4);
DECL(g_h1h, (size_t)B_SZ * N1P); DECL(g_h1l, (size_t)B_SZ * N1P);
DECL(g_h2h, (size_t)B_SZ * N2);  DECL(g_h2l, (size_t)B_SZ * N2);   // reused for h4
DECL(g_h3h, (size_t)B_SZ * N3);  DECL(g_h3l, (size_t)B_SZ * N3);

// ---------------- PTX helpers (all base sm_80-era, no arch-conditional) --
__device__ __forceinline__ uint32_t smem_u32(const void* p) {
    uint32_t a;
    asm("{ .reg .u64 t; cvta.to.shared.u64 t, %1; cvt.u32.u64 %0, t; }" : "=r"(a) : "l"(p));
    return a;
}
__device__ __forceinline__ void cp16(uint32_t s, const void* g) {
    asm volatile("cp.async.cg.shared.global [%0], [%1], 16;" :: "r"(s), "l"(g));
}
__device__ __forceinline__ void cp_commit() {
    asm volatile("cp.async.commit_group;" ::: "memory");
}
__device__ __forceinline__ void cp_wait1() {
    asm volatile("cp.async.wait_group 1;" ::: "memory");
}
__device__ __forceinline__ void cp_wait0() {
    asm volatile("cp.async.wait_group 0;" ::: "memory");
}
__device__ __forceinline__ void ldsm_x4(uint32_t& r0, uint32_t& r1, uint32_t& r2, uint32_t& r3,
                                        uint32_t addr) {
    asm volatile("ldmatrix.sync.aligned.m8n8.x4.shared.b16 {%0,%1,%2,%3}, [%4];"
                 : "=r"(r0), "=r"(r1), "=r"(r2), "=r"(r3) : "r"(addr));
}
__device__ __forceinline__ void mma_bf16(float* c, const uint32_t* a, const uint32_t* b) {
    asm volatile("mma.sync.aligned.m16n8k16.row.col.f32.bf16.bf16.f32 "
                 "{%0,%1,%2,%3}, {%4,%5,%6,%7}, {%8,%9}, {%0,%1,%2,%3};"
                 : "+f"(c[0]), "+f"(c[1]), "+f"(c[2]), "+f"(c[3])
                 : "r"(a[0]), "r"(a[1]), "r"(a[2]), "r"(a[3]), "r"(b[0]), "r"(b[1]));
}
__device__ __forceinline__ uint32_t pack_bf16x2(float a, float b) {
    __nv_bfloat162 t = __floats2bfloat162_rn(a, b);
    return *reinterpret_cast<uint32_t*>(&t);
}

// ---------------- split helpers ------------------------------------------
__device__ __forceinline__ void split_store(float v, __nv_bfloat16* hi, __nv_bfloat16* lo, size_t i) {
    __nv_bfloat16 h = __float2bfloat16(v);
    hi[i] = h;
    lo[i] = __float2bfloat16(v - __bfloat162float(h));
}

// vectorized: 4 consecutive elems -> 8B hi + 8B lo
__device__ __forceinline__ void split4_store(float4 v, __nv_bfloat16* hi, __nv_bfloat16* lo, size_t i) {
    const float h0 = __bfloat162float(__float2bfloat16(v.x));
    const float h1 = __bfloat162float(__float2bfloat16(v.y));
    const float h2 = __bfloat162float(__float2bfloat16(v.z));
    const float h3 = __bfloat162float(__float2bfloat16(v.w));
    uint2 H, L;
    H.x = pack_bf16x2(v.x, v.y);        H.y = pack_bf16x2(v.z, v.w);
    L.x = pack_bf16x2(v.x - h0, v.y - h1);
    L.y = pack_bf16x2(v.z - h2, v.w - h3);
    *reinterpret_cast<uint2*>(hi + i) = H;
    *reinterpret_cast<uint2*>(lo + i) = L;
}

// generic segment: dst [R? x Cp] padded from src [R x C]; li = vec4-aligned elem idx
template <int R, int C, int Cp>
__device__ __forceinline__ void seg_split(const float* __restrict__ src,
                                          __nv_bfloat16* __restrict__ hi,
                                          __nv_bfloat16* __restrict__ lo, size_t li) {
    const int r = (int)(li / Cp), c = (int)(li % Cp);
    float4 v;
    if (r < R && c + 3 < C) {
        v = *reinterpret_cast<const float4*>(src + (size_t)r * C + c);
    } else {
        float e[4];
        #pragma unroll
        for (int k = 0; k < 4; k++)
            e[k] = (r < R && c + k < C) ? src[(size_t)r * C + c + k] : 0.0f;
        v = make_float4(e[0], e[1], e[2], e[3]);
    }
    split4_store(v, hi, lo, li);
}

// segment sizes (elems)
#define S1 ((size_t)N1P * K1P)
#define S2 ((size_t)N2 * N1P)
#define S3 ((size_t)N3 * N2)
#define S4 ((size_t)N4 * N3)
#define S5 ((size_t)NQP * N4)
#define SB1 (S1)
#define SB2 (SB1 + S2)
#define SB3 (SB2 + S3)
#define SB4 (SB3 + S4)
#define SEND (SB4 + S5)

// ONE kernel splits all five weights (compile-time segment dispatch)
__global__ void split_w_all_kernel(const float* __restrict__ w1, const float* __restrict__ w2,
                                   const float* __restrict__ w3, const float* __restrict__ w4,
                                   const float* __restrict__ wq) {
    const size_t i = ((size_t)blockIdx.x * blockDim.x + threadIdx.x) * 4;
    if (i >= SEND) return;
    if      (i < SB1) seg_split<N1R, 132, K1P>(w1, g_w1h, g_w1l, i);
    else if (i < SB2) seg_split<N2, N1R, N1P>(w2, g_w2h, g_w2l, i - SB1);
    else if (i < SB3) seg_split<N3, N2, N2>  (w3, g_w3h, g_w3l, i - SB2);
    else if (i < SB4) seg_split<N4, N3, N3>  (w4, g_w4h, g_w4l, i - SB3);
    else              seg_split<NQR, N4, N4> (wq, g_wqh, g_wql, i - SB4);
}

__global__ void split_x0_kernel(const float* __restrict__ state, const float* __restrict__ pref) {
    const size_t i = ((size_t)blockIdx.x * blockDim.x + threadIdx.x) * 4;
    if (i >= (size_t)B_SZ * K1P) return;
    const int r = (int)(i / K1P), c = (int)(i % K1P);
    float4 v = make_float4(0.f, 0.f, 0.f, 0.f);
    if (c < 128)       v = *reinterpret_cast<const float4*>(state + (size_t)r * 128 + c);
    else if (c == 128) v = *reinterpret_cast<const float4*>(pref + (size_t)r * 4);
    split4_store(v, g_x0h, g_x0l, i);
}

// ---------------- HMMA GEMM: C = A @ W^T (bf16x3 split precision) --------
// A: [8192 x Kp] hi/lo, W: [Npad x Kp] hi/lo, K-major, Kp % 32 == 0.
// CTA tile 128x128, 8 warps (2 m x 4 n), warp tile 64x32.
// SMEM rows padded: 32 bf16 -> 40 (80B, 16B-aligned, LDSM conflict-free).
#define ROWB   80
#define TILEB  (128 * ROWB)       // 10240 per array
#define STAGEB (4 * TILEB)        // 40960 per stage (Ah,Al,Wh,Wl)

template <bool RELU, bool SPLIT_OUT>
__global__ void __launch_bounds__(256)
gemm_hmma(const __nv_bfloat16* __restrict__ Ah, const __nv_bfloat16* __restrict__ Al,
          const __nv_bfloat16* __restrict__ Wh, const __nv_bfloat16* __restrict__ Wl,
          const float* __restrict__ bias, int Kp, int Nreal,
          __nv_bfloat16* __restrict__ outH, __nv_bfloat16* __restrict__ outL, int outKp,
          float* __restrict__ outF)
{
    extern __shared__ char smem[];
    const uint32_t sb = smem_u32(smem);

    const int tid = threadIdx.x, wid = tid >> 5, lane = tid & 31;

    // ---- L2 supertile block remap: 8 n-cols sweep all m before advancing
    const int NBb = gridDim.x, MBb = gridDim.y;
    const int lidb = blockIdx.y * NBb + blockIdx.x;
    const int per  = 8 * MBb;
    const int gi   = lidb / per;
    const int rr   = lidb % per;
    const int remN = NBb - gi * 8;
    const int gN   = remN < 8 ? remN : 8;
    const int bn   = (gi * 8 + rr % gN) * 128;
    const int bm   = (rr / gN) * 128;

    // ---- accumulators: warp 64x32 = 4(m16) x 4(n8) mma tiles
    float acc[4][4][4];
    #pragma unroll
    for (int mi = 0; mi < 4; mi++)
        #pragma unroll
        for (int ni = 0; ni < 4; ni++)
            #pragma unroll
            for (int e = 0; e < 4; e++) acc[mi][ni][e] = 0.0f;

    const int warp_m = wid & 1, warp_n = wid >> 1;

    // ---- per-lane LDSM addressing precompute
    const int mat   = lane >> 3;
    const int mrow8 = lane & 7;
    const int a_rowoff = warp_m * 64 + (mat & 1) * 8 + mrow8;
    const int a_koff   = (mat >> 1) * 16;
    const int b_rowoff = warp_n * 32 + (mat >> 1) * 8 + mrow8;
    const int b_koff   = (mat & 1) * 16;

    const int nch = Kp >> 5;

    auto load_stage = [&](int ch, int buf) {
        const int kk = ch << 5;
        const uint32_t base = sb + buf * STAGEB;
        #pragma unroll
        for (int s = 0; s < 2; s++) {
            const int g   = tid + s * 256;
            const int row = g >> 2;
            const int cb  = (g & 3) << 4;
            const int ce  = cb >> 1;
            const uint32_t so = base + row * ROWB + cb;
            const size_t ga = (size_t)(bm + row) * Kp + kk + ce;
            const size_t gb = (size_t)(bn + row) * Kp + kk + ce;
            cp16(so + 0 * TILEB, Ah + ga);
            cp16(so + 1 * TILEB, Al + ga);
            cp16(so + 2 * TILEB, Wh + gb);
            cp16(so + 3 * TILEB, Wl + gb);
        }
        cp_commit();
    };

    load_stage(0, 0);

    for (int ch = 0; ch < nch; ch++) {
        if (ch + 1 < nch) { load_stage(ch + 1, (ch + 1) & 1); cp_wait1(); }
        else              { cp_wait0(); }
        __syncthreads();

        const uint32_t base = sb + (ch & 1) * STAGEB;
        const uint32_t aHb = base, aLb = base + TILEB;
        const uint32_t wHb = base + 2 * TILEB, wLb = base + 3 * TILEB;

        #pragma unroll
        for (int ks = 0; ks < 2; ks++) {
            const int kb = ks * 32;

            uint32_t a_h[4][4], a_l[4][4];
            #pragma unroll
            for (int mi = 0; mi < 4; mi++) {
                const uint32_t off = (uint32_t)(a_rowoff + mi * 16) * ROWB + kb + a_koff;
                ldsm_x4(a_h[mi][0], a_h[mi][1], a_h[mi][2], a_h[mi][3], aHb + off);
                ldsm_x4(a_l[mi][0], a_l[mi][1], a_l[mi][2], a_l[mi][3], aLb + off);
            }
            uint32_t b_h[4][2], b_l[4][2];
            #pragma unroll
            for (int nj = 0; nj < 2; nj++) {
                const uint32_t off = (uint32_t)(b_rowoff + nj * 16) * ROWB + kb + b_koff;
                ldsm_x4(b_h[nj*2][0], b_h[nj*2][1], b_h[nj*2+1][0], b_h[nj*2+1][1], wHb + off);
                ldsm_x4(b_l[nj*2][0], b_l[nj*2][1], b_l[nj*2+1][0], b_l[nj*2+1][1], wLb + off);
            }

            #pragma unroll
            for (int mi = 0; mi < 4; mi++)
                #pragma unroll
                for (int ni = 0; ni < 4; ni++) {
                    mma_bf16(acc[mi][ni], a_h[mi], b_h[ni]);
                    mma_bf16(acc[mi][ni], a_h[mi], b_l[ni]);
                    mma_bf16(acc[mi][ni], a_l[mi], b_h[ni]);
                }
        }
        __syncthreads();
    }

    // ---- epilogue: bias + ReLU; packed bf16x2 stores for split path
    const int qrow = lane >> 2, qcol = (lane & 3) * 2;
    #pragma unroll
    for (int mi = 0; mi < 4; mi++) {
        #pragma unroll
        for (int ni = 0; ni < 4; ni++) {
            const int r0 = bm + warp_m * 64 + mi * 16 + qrow;
            const int c0 = bn + warp_n * 32 + ni * 8 + qcol;
            const float bv0 = (c0     < Nreal) ? bias[c0]     : 0.0f;
            const float bv1 = (c0 + 1 < Nreal) ? bias[c0 + 1] : 0.0f;
            #pragma unroll
            for (int half = 0; half < 2; half++) {
                const int row = r0 + half * 8;
                float v0 = acc[mi][ni][half * 2 + 0] + bv0;
                float v1 = acc[mi][ni][half * 2 + 1] + bv1;
                if (RELU) { v0 = fmaxf(v0, 0.0f); v1 = fmaxf(v1, 0.0f); }
                if (SPLIT_OUT) {
                    const size_t o = (size_t)row * outKp + c0;
                    const float h0 = __bfloat162float(__float2bfloat16(v0));
                    const float h1 = __bfloat162float(__float2bfloat16(v1));
                    *reinterpret_cast<uint32_t*>(outH + o) = pack_bf16x2(v0, v1);
                    *reinterpret_cast<uint32_t*>(outL + o) = pack_bf16x2(v0 - h0, v1 - h1);
                } else {
                    if (c0     < Nreal) outF[(size_t)row * Nreal + c0]     = v0;
                    if (c0 + 1 < Nreal) outF[(size_t)row * Nreal + c0 + 1] = v1;
                }
            }
        }
    }
}

// ---------------- envelope operator H ------------------------------------
__global__ void envelope_kernel(const float* __restrict__ q,
                                const float* __restrict__ pref,
                                float* __restrict__ hq)
{
    int i = blockIdx.x * blockDim.x + threadIdx.x;
    if (i >= B_SZ) return;
    const float4 p = *reinterpret_cast<const float4*>(&pref[i * 4]);
    const float* qi = q + (size_t)i * NQR;
    float best = -CUDART_INF_F;
    int ba = 0;
    #pragma unroll
    for (int a = 0; a < A_SZ; a++) {
        const float4 qa = *reinterpret_cast<const float4*>(&qi[a * 4]);
        const float ip = qa.x * p.x + qa.y * p.y + qa.z * p.z + qa.w * p.w;
        if (ip > best) { best = ip; ba = a; }
    }
    *reinterpret_cast<float4*>(&hq[i * 4]) = *reinterpret_cast<const float4*>(&qi[ba * 4]);
}

// ---------------- launch --------------------------------------------------
extern "C" void kernel_launch(void* const* d_in, const int* in_sizes, int n_in,
                              void* d_out, int out_size)
{
    const float* state = (const float*)d_in[0];
    const float* pref  = (const float*)d_in[1];
    const float* w1 = (const float*)d_in[2];  const float* b1 = (const float*)d_in[3];
    const float* w2 = (const float*)d_in[4];  const float* b2 = (const float*)d_in[5];
    const float* w3 = (const float*)d_in[6];  const float* b3 = (const float*)d_in[7];
    const float* w4 = (const float*)d_in[8];  const float* b4 = (const float*)d_in[9];
    const float* wq = (const float*)d_in[10]; const float* bq = (const float*)d_in[11];

    float* out_hq = (float*)d_out;
    float* out_q  = (float*)d_out + (size_t)B_SZ * 4;

    #define SYM(p, s) __nv_bfloat16* p; cudaGetSymbolAddress((void**)&p, s)
    SYM(x0h, g_x0h); SYM(x0l, g_x0l);
    SYM(w1h, g_w1h); SYM(w1l, g_w1l);
    SYM(w2h, g_w2h); SYM(w2l, g_w2l);
    SYM(w3h, g_w3h); SYM(w3l, g_w3l);
    SYM(w4h, g_w4h); SYM(w4l, g_w4l);
    SYM(wqh, g_wqh); SYM(wql, g_wql);
    SYM(h1h, g_h1h); SYM(h1l, g_h1l);
    SYM(h2h, g_h2h); SYM(h2l, g_h2l);
    SYM(h3h, g_h3h); SYM(h3l, g_h3l);
    #undef SYM

    const int SMEM = 2 * STAGEB;   // 81920 B double-buffered
    cudaFuncSetAttribute(gemm_hmma<true,  true >, cudaFuncAttributeMaxDynamicSharedMemorySize, SMEM);
    cudaFuncSetAttribute(gemm_hmma<false, false>, cudaFuncAttributeMaxDynamicSharedMemorySize, SMEM);

    // ---- split/pad inputs & weights (launch #1, #2) ----
    {
        const long long nx0 = (long long)B_SZ * K1P / 4;
        split_x0_kernel<<<(int)((nx0 + 255) / 256), 256>>>(state, pref);
        const long long nw = (long long)(SEND / 4);
        split_w_all_kernel<<<(int)((nw + 255) / 256), 256>>>(w1, w2, w3, w4, wq);
    }

    const int MB = B_SZ / 128;  // 64

    // launches #3-#7: gemm1..gemmq (ncu -s 5 -c 1 captures #6 = layer-4 gemm)
    gemm_hmma<true, true><<<dim3(N1P / 128, MB), 256, SMEM>>>(
        x0h, x0l, w1h, w1l, b1, K1P, N1R, h1h, h1l, N1P, nullptr);
    gemm_hmma<true, true><<<dim3(N2 / 128, MB), 256, SMEM>>>(
        h1h, h1l, w2h, w2l, b2, N1P, N2, h2h, h2l, N2, nullptr);
    gemm_hmma<true, true><<<dim3(N3 / 128, MB), 256, SMEM>>>(
        h2h, h2l, w3h, w3l, b3, N2, N3, h3h, h3l, N3, nullptr);
    gemm_hmma<true, true><<<dim3(N4 / 128, MB), 256, SMEM>>>(
        h3h, h3l, w4h, w4l, b4, N3, N4, h2h, h2l, N4, nullptr);
    gemm_hmma<false, false><<<dim3(NQP / 128, MB), 256, SMEM>>>(
        h2h, h2l, wqh, wql, bq, N4, NQR, nullptr, nullptr, 0, out_q);

    envelope_kernel<<<(B_SZ + 255) / 256, 256>>>(out_q, pref, out_hq);
}